// round 17
// baseline (speedup 1.0000x reference)
#include <cuda_runtime.h>
#include <cuda_fp16.h>
#include <mma.h>
#include <math.h>

using namespace nvcuda;

#define NN 20000
#define EE 80000
#define GG 1000
#define FTOT 16
#define CSD 5
#define FCIN 75

// ---------------- device scratch (allocation-free contract) ----------------
__device__ float g_hA[NN * 64];
__device__ float g_hB[NN * 64];
__device__ __half g_hH[NN * 64];                 // fp16 h, padded [n][MI_P]
__device__ __half g_w2h[64 * 128 * 64];          // fp16 w2, layout [i][q], q = k*MO+o
__device__ float g_hid[(size_t)EE * 128];
__device__ __half g_Ph[(size_t)NN * 128 * 64];   // plain layout: n*COLS + k*MO + o
__device__ float g_R[NN * 64];
__device__ float g_agg[NN * 64];
__device__ float g_gsum[GG * FCIN];
__device__ float g_gcnt[GG];
// CSR by src (edge_index constant across layers -> build once per launch)
__device__ int g_deg[NN];
__device__ int g_off[NN + 1];
__device__ int g_pos[NN];
__device__ int g_eord[EE];

__device__ __forceinline__ float* hbuf(int s) { return s ? g_hB : g_hA; }
__device__ __forceinline__ float elu_f(float x) { return x > 0.f ? x : (expf(x) - 1.f); }

// ---------------- CSR build ----------------

__global__ void zero_deg_kernel() {
    int idx = blockIdx.x * blockDim.x + threadIdx.x;
    if (idx < NN) g_deg[idx] = 0;
}

__global__ void deg_kernel(const int* __restrict__ ei) {
    int e = blockIdx.x * blockDim.x + threadIdx.x;
    if (e < EE) atomicAdd(&g_deg[ei[e]], 1);
}

__global__ void scan_kernel() {
    __shared__ int part[256];
    int t = threadIdx.x;
    const int C = (NN + 255) / 256;
    int s = 0;
    for (int i = 0; i < C; i++) {
        int n = t * C + i;
        if (n < NN) s += g_deg[n];
    }
    part[t] = s;
    __syncthreads();
    for (int d = 1; d < 256; d <<= 1) {
        int v = (t >= d) ? part[t - d] : 0;
        __syncthreads();
        part[t] += v;
        __syncthreads();
    }
    int base = (t == 0) ? 0 : part[t - 1];
    for (int i = 0; i < C; i++) {
        int n = t * C + i;
        if (n < NN) {
            g_off[n] = base;
            g_pos[n] = base;
            base += g_deg[n];
        }
    }
    if (t == 255) g_off[NN] = base;
}

__global__ void fill_kernel(const int* __restrict__ ei) {
    int e = blockIdx.x * blockDim.x + threadIdx.x;
    if (e < EE) {
        int p = atomicAdd(&g_pos[ei[e]], 1);
        g_eord[p] = e;
    }
}

// ---------------- kernels ----------------

// h0 (fp32 compact, CSD wide) + fp16 padded copy (16 wide) in one pass
__global__ void init_h0_kernel(const float* __restrict__ x) {
    int idx = blockIdx.x * blockDim.x + threadIdx.x;
    if (idx >= NN * 16) return;
    int n = idx / 16, i = idx % 16;
    float v = (i < CSD) ? x[n * FTOT + i] : 0.f;
    if (i < CSD) g_hA[n * CSD + i] = v;
    g_hH[idx] = __float2half(v);
}

// hid[e,k] = relu(b1[k] + sum_a ea[e,a]*w1[a,k])
__global__ void hid_kernel(const float* __restrict__ ea,
                           const float* __restrict__ w1,
                           const float* __restrict__ b1) {
    int e = blockIdx.x;
    int k = threadIdx.x;
    __shared__ float a[5];
    if (k < 5) a[k] = ea[e * 5 + k];
    __syncthreads();
    float s = b1[k];
#pragma unroll
    for (int i = 0; i < 5; i++) s = fmaf(a[i], w1[i * 128 + k], s);
    g_hid[(size_t)e * 128 + k] = fmaxf(s, 0.f);
}

// w2 -> g_w2h[i*COLS + q] (fp16, q = k*MO + o, zero-padded i >= MI)
template <int MI, int MO, int MI_P>
__global__ void convw2_kernel(const float* __restrict__ w2) {
    const int COLS = 128 * MO;
    int idx = blockIdx.x * blockDim.x + threadIdx.x;
    if (idx >= MI_P * COLS) return;
    int i = idx / COLS, q = idx % COLS;
    float v = 0.f;
    if (i < MI) {
        int k = q / MO;
        int o = q % MO;
        v = w2[(k * MI + i) * MO + o];
    }
    g_w2h[idx] = __float2half(v);
}

// P = h @ w2  (fp16 HMMA wmma m16n16k16, fp32 accum) -> fp16 g_Ph (plain [n][k][o])
template <int MI_P, int MO>
__global__ __launch_bounds__(256) void p4_kernel() {
    const int COLS = 128 * MO;
    __shared__ __half Ah[64 * MI_P];
    __shared__ float CsBs[64 * 128];         // B tile (fp16) during k-loop; C staging (fp32) after
    __half* Bh = (__half*)CsBs;
    int nb = blockIdx.y * 64;
    int qb = blockIdx.x * 128;
    int t = threadIdx.x;

    {
        const int AV = 64 * MI_P / 8;
        uint4* Av = (uint4*)Ah;
        for (int idx = t; idx < AV; idx += 256) {
            int n = idx / (MI_P / 8);
            int node = nb + n;
            if (node < NN)
                Av[idx] = ((const uint4*)g_hH)[(size_t)node * (MI_P / 8) + (idx % (MI_P / 8))];
            else
                Av[idx] = make_uint4(0, 0, 0, 0);
        }
    }
    {
        uint4* Bv = (uint4*)Bh;
        for (int idx = t; idx < MI_P * 16; idx += 256) {
            int i = idx / 16, v = idx % 16;
            Bv[idx] = ((const uint4*)(g_w2h + (size_t)i * COLS + qb))[v];
        }
    }
    __syncthreads();

    int wid = t >> 5;
    int mt = wid & 3;
    int nh = wid >> 2;

    wmma::fragment<wmma::accumulator, 16, 16, 16, float> c_frag[4];
#pragma unroll
    for (int j = 0; j < 4; j++) wmma::fill_fragment(c_frag[j], 0.f);

#pragma unroll
    for (int ks = 0; ks < MI_P / 16; ks++) {
        wmma::fragment<wmma::matrix_a, 16, 16, 16, __half, wmma::row_major> a_frag;
        wmma::load_matrix_sync(a_frag, &Ah[(mt * 16) * MI_P + ks * 16], MI_P);
#pragma unroll
        for (int j = 0; j < 4; j++) {
            wmma::fragment<wmma::matrix_b, 16, 16, 16, __half, wmma::row_major> b_frag;
            wmma::load_matrix_sync(b_frag, &Bh[(ks * 16) * 128 + (nh * 64 + j * 16)], 128);
            wmma::mma_sync(c_frag[j], a_frag, b_frag, c_frag[j]);
        }
    }
    __syncthreads();

#pragma unroll
    for (int j = 0; j < 4; j++)
        wmma::store_matrix_sync(&CsBs[(mt * 16) * 128 + (nh * 64 + j * 16)], c_frag[j], 128,
                                wmma::mem_row_major);
    __syncthreads();

    for (int idx = t; idx < 64 * 64; idx += 256) {
        int row = idx >> 6, cp = idx & 63;
        int node = nb + row;
        if (node < NN) {
            __half2 h2 = __floats2half2_rn(CsBs[row * 128 + 2 * cp], CsBs[row * 128 + 2 * cp + 1]);
            *(unsigned*)&g_Ph[(size_t)node * COLS + qb + 2 * cp] = *(unsigned*)&h2;
        }
    }
}

// R[n,o] = h[n]@b2[:,o] ; agg[n,o] = bias[o] + h[n]@root[:,o]
template <int MI, int MO>
__global__ void rb_kernel(const float* __restrict__ b2,
                          const float* __restrict__ root,
                          const float* __restrict__ bias, int insel) {
    int idx = blockIdx.x * blockDim.x + threadIdx.x;
    if (idx >= NN * MO) return;
    int n = idx / MO, o = idx % MO;
    const float* h = hbuf(insel);
    float sr = 0.f, sa = bias[o];
#pragma unroll
    for (int i = 0; i < MI; i++) {
        float hv = h[n * MI + i];
        sr = fmaf(hv, b2[i * MO + o], sr);
        sa = fmaf(hv, root[i * MO + o], sa);
    }
    g_R[n * MO + o] = sr;
    g_agg[n * MO + o] = sa;
}

// CSR-grouped edge stage: one block per src node; P[src] staged in smem once.
// msg[e,o] = R[src,o] + sum_k hid[e,k]*P[src,k,o]; atomic scatter to agg[dst].
template <int MO>
__global__ __launch_bounds__(64) void edge3_kernel(const int* __restrict__ ei) {
    __shared__ float Ps[128 * MO];
    __shared__ float hid_s[128];
    int n = blockIdx.x;
    int beg = g_off[n], end = g_off[n + 1];
    if (beg == end) return;
    int t = threadIdx.x;  // MO threads
    const int COLS = 128 * MO;

    const __half2* Pr = (const __half2*)&g_Ph[(size_t)n * COLS];
    for (int idx = t; idx < COLS / 2; idx += MO) {
        float2 f = __half22float2(Pr[idx]);
        *(float2*)&Ps[2 * idx] = f;
    }
    float Rv = g_R[n * MO + t];
    __syncthreads();

    for (int p = beg; p < end; p++) {
        int e = g_eord[p];
        int dst = ei[EE + e];
        for (int i = t; i < 128; i += MO) hid_s[i] = g_hid[(size_t)e * 128 + i];
        __syncthreads();
        float acc = Rv;
#pragma unroll
        for (int k = 0; k < 128; k++) acc = fmaf(hid_s[k], Ps[k * MO + t], acc);
        atomicAdd(&g_agg[dst * MO + t], acc);
        __syncthreads();
    }
}

// h_out = elu(agg); also produce fp16 copy for the next layer's GEMM (MO == next MI, no pad)
template <int MO, int WRITE_H16>
__global__ void elu_kernel(int outsel) {
    int idx = blockIdx.x * blockDim.x + threadIdx.x;
    if (idx >= NN * MO) return;
    float v = elu_f(g_agg[idx]);
    hbuf(outsel)[idx] = v;
    if (WRITE_H16) g_hH[idx] = __float2half(v);
}

__global__ void zero_pool_kernel() {
    int idx = blockIdx.x * blockDim.x + threadIdx.x;
    if (idx < GG * FCIN) g_gsum[idx] = 0.f;
    if (idx < GG) g_gcnt[idx] = 0.f;
}

__global__ void pool_scatter_kernel(const float* __restrict__ x,
                                    const int* __restrict__ batch, int hsel) {
    int idx = blockIdx.x * blockDim.x + threadIdx.x;
    if (idx >= NN * FCIN) return;
    int n = idx / FCIN, d = idx % FCIN;
    const float* h = hbuf(hsel);
    float v = (d < 64) ? h[n * 64 + d] : x[n * FTOT + CSD + (d - 64)];
    int b = batch[n];
    atomicAdd(&g_gsum[b * FCIN + d], v);
    if (d == 0) atomicAdd(&g_gcnt[b], 1.f);
}

__global__ void mlp_kernel(const float* __restrict__ fc1w, const float* __restrict__ fc1b,
                           const float* __restrict__ fc2w, const float* __restrict__ fc2b,
                           const float* __restrict__ fc3w, const float* __restrict__ fc3b,
                           float* __restrict__ out) {
    int g = blockIdx.x;
    int t = threadIdx.x;  // 32
    __shared__ float gv[FCIN], a1[32], a2[16];
    float cnt = fmaxf(g_gcnt[g], 1.f);
    for (int i = t; i < FCIN; i += 32) gv[i] = g_gsum[g * FCIN + i] / cnt;
    __syncthreads();
    {
        float s = fc1b[t];
        for (int i = 0; i < FCIN; i++) s = fmaf(gv[i], fc1w[i * 32 + t], s);
        a1[t] = elu_f(s);
    }
    __syncthreads();
    if (t < 16) {
        float s = fc2b[t];
#pragma unroll
        for (int i = 0; i < 32; i++) s = fmaf(a1[i], fc2w[i * 16 + t], s);
        a2[t] = elu_f(s);
    }
    __syncthreads();
    if (t == 0) {
        float s = fc3b[0];
#pragma unroll
        for (int i = 0; i < 16; i++) s = fmaf(a2[i], fc3w[i], s);
        out[g] = s;
    }
}

// ---------------- host side ----------------

template <int MI, int MO, int MI_P, int WRITE_H16>
static void run_layer(const float* ea, const int* ei,
                      const float* w1, const float* b1,
                      const float* w2, const float* b2,
                      const float* root, const float* bias,
                      int insel, int outsel) {
    hid_kernel<<<EE, 128>>>(ea, w1, b1);
    convw2_kernel<MI, MO, MI_P><<<(MI_P * 128 * MO + 255) / 256, 256>>>(w2);
    dim3 pg(MO, (NN + 63) / 64);
    p4_kernel<MI_P, MO><<<pg, 256>>>();
    rb_kernel<MI, MO><<<(NN * MO + 255) / 256, 256>>>(b2, root, bias, insel);
    edge3_kernel<MO><<<NN, MO>>>(ei);
    elu_kernel<MO, WRITE_H16><<<(NN * MO + 255) / 256, 256>>>(outsel);
}

extern "C" void kernel_launch(void* const* d_in, const int* in_sizes, int n_in,
                              void* d_out, int out_size) {
    const float* x  = (const float*)d_in[0];
    const int*   ei = (const int*)d_in[1];
    const float* ea = (const float*)d_in[2];
    const int*   batch = (const int*)d_in[3];

    const float* c1w1 = (const float*)d_in[4];
    const float* c1b1 = (const float*)d_in[5];
    const float* c1w2 = (const float*)d_in[6];
    const float* c1b2 = (const float*)d_in[7];
    const float* c1root = (const float*)d_in[8];
    const float* c1bias = (const float*)d_in[9];

    const float* c2w1 = (const float*)d_in[10];
    const float* c2b1 = (const float*)d_in[11];
    const float* c2w2 = (const float*)d_in[12];
    const float* c2b2 = (const float*)d_in[13];
    const float* c2root = (const float*)d_in[14];
    const float* c2bias = (const float*)d_in[15];

    const float* c3w1 = (const float*)d_in[16];
    const float* c3b1 = (const float*)d_in[17];
    const float* c3w2 = (const float*)d_in[18];
    const float* c3b2 = (const float*)d_in[19];
    const float* c3root = (const float*)d_in[20];
    const float* c3bias = (const float*)d_in[21];

    const float* fc1w = (const float*)d_in[22];
    const float* fc1b = (const float*)d_in[23];
    const float* fc2w = (const float*)d_in[24];
    const float* fc2b = (const float*)d_in[25];
    const float* fc3w = (const float*)d_in[26];
    const float* fc3b = (const float*)d_in[27];

    // h0: fp32 compact + fp16 padded (16) in one pass
    init_h0_kernel<<<(NN * 16 + 255) / 256, 256>>>(x);

    // build src-CSR once (edge_index constant across layers)
    zero_deg_kernel<<<(NN + 255) / 256, 256>>>();
    deg_kernel<<<(EE + 255) / 256, 256>>>(ei);
    scan_kernel<<<1, 256>>>();
    fill_kernel<<<(EE + 255) / 256, 256>>>(ei);

    run_layer<5, 32, 16, 1>(ea, ei, c1w1, c1b1, c1w2, c1b2, c1root, c1bias, 0, 1);
    run_layer<32, 64, 32, 1>(ea, ei, c2w1, c2b1, c2w2, c2b2, c2root, c2bias, 1, 0);
    run_layer<64, 64, 64, 0>(ea, ei, c3w1, c3b1, c3w2, c3b2, c3root, c3bias, 0, 1);

    zero_pool_kernel<<<(GG * FCIN + 255) / 256, 256>>>();
    pool_scatter_kernel<<<(NN * FCIN + 255) / 256, 256>>>(x, batch, 1);
    mlp_kernel<<<GG, 32>>>(fc1w, fc1b, fc2w, fc2b, fc3w, fc3b, (float*)d_out);
}